// round 1
// baseline (speedup 1.0000x reference)
#include <cuda_runtime.h>

#define IN_DIM   8192
#define OUT_DIM  16384
#define TOPK     327
#define ROW_SPLITS 32
#define COL_BLOCKS 16          // 16 blocks * 256 thr * 4 cols = 16384 cols

__device__ int g_active[IN_DIM];
__device__ int g_nactive;
__device__ int g_overlap[OUT_DIM];

// ---------------------------------------------------------------------------
// Kernel 1: compact active-row indices (order irrelevant for the sum), zero
// the overlap accumulator.
// ---------------------------------------------------------------------------
__global__ void prep_kernel(const int* __restrict__ x) {
    __shared__ int s_cnt;
    int tid = threadIdx.x;
    if (tid == 0) s_cnt = 0;
    __syncthreads();
    for (int i = tid; i < IN_DIM; i += blockDim.x) {
        if (x[i] != 0) {
            int pos = atomicAdd(&s_cnt, 1);
            g_active[pos] = i;
        }
    }
    for (int j = tid; j < OUT_DIM; j += blockDim.x) g_overlap[j] = 0;
    __syncthreads();
    if (tid == 0) g_nactive = s_cnt;
}

// ---------------------------------------------------------------------------
// Kernel 2: binarized GEMV over active rows only.
// grid = (COL_BLOCKS, ROW_SPLITS), block = 256.
// Each thread: 4 consecutive columns (one float4 per row), ~nactive/32 rows.
// round(p) for p in [0,1) with round-half-even == (p > 0.5f).
// ---------------------------------------------------------------------------
__global__ void gemv_kernel(const float* __restrict__ p) {
    int col = (blockIdx.x * blockDim.x + threadIdx.x) * 4;
    int na = g_nactive;
    int chunk = (na + ROW_SPLITS - 1) / ROW_SPLITS;
    int r0 = blockIdx.y * chunk;
    int r1 = min(r0 + chunk, na);

    int c0 = 0, c1 = 0, c2 = 0, c3 = 0;
    const float* pc = p + col;

    int r = r0;
    // 4-way unroll for memory-level parallelism
    for (; r + 4 <= r1; r += 4) {
        int i0 = g_active[r + 0];
        int i1 = g_active[r + 1];
        int i2 = g_active[r + 2];
        int i3 = g_active[r + 3];
        float4 v0 = *reinterpret_cast<const float4*>(pc + (size_t)i0 * OUT_DIM);
        float4 v1 = *reinterpret_cast<const float4*>(pc + (size_t)i1 * OUT_DIM);
        float4 v2 = *reinterpret_cast<const float4*>(pc + (size_t)i2 * OUT_DIM);
        float4 v3 = *reinterpret_cast<const float4*>(pc + (size_t)i3 * OUT_DIM);
        c0 += (v0.x > 0.5f) + (v1.x > 0.5f) + (v2.x > 0.5f) + (v3.x > 0.5f);
        c1 += (v0.y > 0.5f) + (v1.y > 0.5f) + (v2.y > 0.5f) + (v3.y > 0.5f);
        c2 += (v0.z > 0.5f) + (v1.z > 0.5f) + (v2.z > 0.5f) + (v3.z > 0.5f);
        c3 += (v0.w > 0.5f) + (v1.w > 0.5f) + (v2.w > 0.5f) + (v3.w > 0.5f);
    }
    for (; r < r1; r++) {
        int i0 = g_active[r];
        float4 v0 = *reinterpret_cast<const float4*>(pc + (size_t)i0 * OUT_DIM);
        c0 += (v0.x > 0.5f);
        c1 += (v0.y > 0.5f);
        c2 += (v0.z > 0.5f);
        c3 += (v0.w > 0.5f);
    }

    if (c0) atomicAdd(&g_overlap[col + 0], c0);
    if (c1) atomicAdd(&g_overlap[col + 1], c1);
    if (c2) atomicAdd(&g_overlap[col + 2], c2);
    if (c3) atomicAdd(&g_overlap[col + 3], c3);
}

// ---------------------------------------------------------------------------
// Kernel 3: exact top-K with jax.lax.top_k tie semantics (lower index first).
// Single block, 1024 threads.
//   Phase A: shared histogram of overlap values (bins 0..8192).
//   Phase B: block suffix-scan to find threshold T (K-th largest value) and
//            R = K - count(> T) tie slots.
//   Phase C: 16 ordered segment scans over the 16384 columns so the R tie
//            slots go to the LOWEST tie indices. Write dense 0/1 floats.
// ---------------------------------------------------------------------------
__global__ void topk_kernel(float* __restrict__ out) {
    __shared__ int s_hist[IN_DIM + 1];   // 8193 bins
    __shared__ int s_scan[1024];
    __shared__ int s_T, s_R, s_base;

    int tid = threadIdx.x;

    for (int i = tid; i <= IN_DIM; i += 1024) s_hist[i] = 0;
    __syncthreads();

    int ov[16];
#pragma unroll
    for (int s = 0; s < 16; s++) {
        ov[s] = g_overlap[s * 1024 + tid];
        atomicAdd(&s_hist[ov[s]], 1);
    }
    __syncthreads();

    // --- Phase B: threshold search ---
    // thread t owns bins [8t, 8t+7]; thread 1023 additionally owns bin 8192.
    int b0 = tid * 8;
    int csum = 0;
#pragma unroll
    for (int k = 0; k < 8; k++) csum += s_hist[b0 + k];
    if (tid == 1023) csum += s_hist[IN_DIM];

    // inclusive suffix scan of chunk sums: s_scan[u] after scan (indexed by
    // reversed position) gives sum over chunks >= t.
    s_scan[1023 - tid] = csum;           // reverse so a prefix scan = suffix scan
    __syncthreads();
    for (int off = 1; off < 1024; off <<= 1) {
        int v = 0;
        if (tid >= off) v = s_scan[tid - off];
        __syncthreads();
        s_scan[tid] += v;
        __syncthreads();
    }
    // SUF(t) = count of elements with value >= first bin of chunk t
    //        = s_scan[1023 - t].  Exclusive-above for chunk t: SUF(t+1).
    int above = (tid == 1023) ? 0 : s_scan[1023 - (tid + 1)];

    // walk own bins top-down; T = max v with count(>= v) >= K
    {
        int running = above;
        int top = (tid == 1023) ? IN_DIM : (b0 + 7);
        for (int v = top; v >= b0; v--) {
            int prev = running;          // count(> v) == count(>= v+1)
            running += s_hist[v];
            if (prev < TOPK && running >= TOPK) {
                s_T = v;
                s_R = TOPK - prev;       // tie slots at value T
            }
        }
    }
    if (tid == 0) s_base = 0;
    __syncthreads();

    int T = s_T;
    int R = s_R;

    // --- Phase C: ordered tie resolution + output ---
#pragma unroll 1
    for (int s = 0; s < 16; s++) {
        int flag = (ov[s] == T) ? 1 : 0;
        s_scan[tid] = flag;
        __syncthreads();
        for (int off = 1; off < 1024; off <<= 1) {
            int v = 0;
            if (tid >= off) v = s_scan[tid - off];
            __syncthreads();
            s_scan[tid] += v;
            __syncthreads();
        }
        int excl = s_scan[tid] - flag;
        int total = s_scan[1023];
        int rank = s_base + excl;        // ordinal among ties, in index order

        float val = 0.0f;
        if (ov[s] > T) val = 1.0f;
        else if (flag && rank < R) val = 1.0f;
        out[s * 1024 + tid] = val;

        __syncthreads();
        if (tid == 0) s_base += total;
        __syncthreads();
    }
}

extern "C" void kernel_launch(void* const* d_in, const int* in_sizes, int n_in,
                              void* d_out, int out_size) {
    // robust input binding: x has IN_DIM elements, p has IN_DIM*OUT_DIM
    const int*   x = (const int*)d_in[0];
    const float* p = (const float*)d_in[1];
    if (in_sizes[0] != IN_DIM) {
        x = (const int*)d_in[1];
        p = (const float*)d_in[0];
    }
    float* out = (float*)d_out;

    prep_kernel<<<1, 1024>>>(x);
    dim3 grid(COL_BLOCKS, ROW_SPLITS);
    gemv_kernel<<<grid, 256>>>(p);
    topk_kernel<<<1, 1024>>>(out);
}

// round 3
// speedup vs baseline: 1.3351x; 1.3351x over previous
#include <cuda_runtime.h>

#define IN_DIM   8192
#define OUT_DIM  16384
#define TOPK     327
#define ROW_SPLITS 32
#define COL_BLOCKS 16          // 16 blocks * 256 thr * 4 cols = 16384 cols

__device__ int g_active[IN_DIM];
__device__ int g_nactive;
__device__ int g_overlap[OUT_DIM];

__device__ __forceinline__ int warp_incl_scan(int v) {
    int lane = threadIdx.x & 31;
#pragma unroll
    for (int o = 1; o < 32; o <<= 1) {
        int n = __shfl_up_sync(0xffffffffu, v, o);
        if (lane >= o) v += n;
    }
    return v;
}

// ---------------------------------------------------------------------------
// Kernel 1: block 0 compacts active rows; blocks 1..16 zero g_overlap.
// ---------------------------------------------------------------------------
__global__ void prep_kernel(const int* __restrict__ x) {
    if (blockIdx.x == 0) {
        __shared__ int s_cnt;
        int tid = threadIdx.x;
        if (tid == 0) s_cnt = 0;
        __syncthreads();
        for (int i = tid; i < IN_DIM; i += blockDim.x) {
            if (x[i] != 0) {
                int pos = atomicAdd(&s_cnt, 1);
                g_active[pos] = i;
            }
        }
        __syncthreads();
        if (tid == 0) g_nactive = s_cnt;
    } else {
        int j = (blockIdx.x - 1) * 1024 + threadIdx.x;
        g_overlap[j] = 0;
    }
}

// ---------------------------------------------------------------------------
// Kernel 2: binarized GEMV over active rows only (DRAM-bound, ~256MB).
// round(p) for p in [0,1) with round-half-even == (p > 0.5f).
// ---------------------------------------------------------------------------
__global__ void gemv_kernel(const float* __restrict__ p) {
    int col = (blockIdx.x * blockDim.x + threadIdx.x) * 4;
    int na = g_nactive;
    int chunk = (na + ROW_SPLITS - 1) / ROW_SPLITS;
    int r0 = blockIdx.y * chunk;
    int r1 = min(r0 + chunk, na);

    int c0 = 0, c1 = 0, c2 = 0, c3 = 0;
    const float* pc = p + col;

    int r = r0;
    for (; r + 4 <= r1; r += 4) {
        int i0 = g_active[r + 0];
        int i1 = g_active[r + 1];
        int i2 = g_active[r + 2];
        int i3 = g_active[r + 3];
        float4 v0 = *reinterpret_cast<const float4*>(pc + (size_t)i0 * OUT_DIM);
        float4 v1 = *reinterpret_cast<const float4*>(pc + (size_t)i1 * OUT_DIM);
        float4 v2 = *reinterpret_cast<const float4*>(pc + (size_t)i2 * OUT_DIM);
        float4 v3 = *reinterpret_cast<const float4*>(pc + (size_t)i3 * OUT_DIM);
        c0 += (v0.x > 0.5f) + (v1.x > 0.5f) + (v2.x > 0.5f) + (v3.x > 0.5f);
        c1 += (v0.y > 0.5f) + (v1.y > 0.5f) + (v2.y > 0.5f) + (v3.y > 0.5f);
        c2 += (v0.z > 0.5f) + (v1.z > 0.5f) + (v2.z > 0.5f) + (v3.z > 0.5f);
        c3 += (v0.w > 0.5f) + (v1.w > 0.5f) + (v2.w > 0.5f) + (v3.w > 0.5f);
    }
    for (; r < r1; r++) {
        int i0 = g_active[r];
        float4 v0 = *reinterpret_cast<const float4*>(pc + (size_t)i0 * OUT_DIM);
        c0 += (v0.x > 0.5f);
        c1 += (v0.y > 0.5f);
        c2 += (v0.z > 0.5f);
        c3 += (v0.w > 0.5f);
    }

    if (c0) atomicAdd(&g_overlap[col + 0], c0);
    if (c1) atomicAdd(&g_overlap[col + 1], c1);
    if (c2) atomicAdd(&g_overlap[col + 2], c2);
    if (c3) atomicAdd(&g_overlap[col + 3], c3);
}

// ---------------------------------------------------------------------------
// Kernel 3: exact top-K with jax.lax.top_k tie semantics (lower index first).
// Single block, 1024 threads, shuffle/ballot scans (~12 barriers total).
// ---------------------------------------------------------------------------
__global__ void topk_kernel(float* __restrict__ out) {
    __shared__ int s_hist[IN_DIM + 1];   // 8193 bins
    __shared__ int s_scan[1024];
    __shared__ int s_warp[32];
    __shared__ int s_cnt[512];           // per (segment, warp) tie counts
    __shared__ int s_T, s_R;

    int tid  = threadIdx.x;
    int lane = tid & 31;
    int wid  = tid >> 5;

    for (int i = tid; i <= IN_DIM; i += 1024) s_hist[i] = 0;
    __syncthreads();

    // --- Phase A: histogram ---
    int ov[16];
#pragma unroll
    for (int s = 0; s < 16; s++) {
        ov[s] = g_overlap[s * 1024 + tid];
        atomicAdd(&s_hist[ov[s]], 1);
    }
    __syncthreads();

    // --- Phase B: threshold search ---
    // thread t owns bins [8t, 8t+7]; thread 1023 also owns bin 8192.
    int b0 = tid * 8;
    int csum = 0;
#pragma unroll
    for (int k = 0; k < 8; k++) csum += s_hist[b0 + k];
    if (tid == 1023) csum += s_hist[IN_DIM];

    // reversed inclusive scan => suffix sums. s_scan[j] will hold
    // P[j] = sum over chunks >= (1023-j).
    s_scan[1023 - tid] = csum;
    __syncthreads();
    {
        int v = s_scan[tid];
        int inc = warp_incl_scan(v);
        if (lane == 31) s_warp[wid] = inc;
        __syncthreads();
        if (wid == 0) {
            int wv = s_warp[lane];
            s_warp[lane] = warp_incl_scan(wv);
        }
        __syncthreads();
        int add = (wid > 0) ? s_warp[wid - 1] : 0;
        s_scan[tid] = inc + add;
    }
    __syncthreads();

    // count strictly above chunk t = SUF(t+1) = P[1022 - t]
    int above = (tid == 1023) ? 0 : s_scan[1022 - tid];

    {
        int running = above;
        int top = (tid == 1023) ? IN_DIM : (b0 + 7);
        for (int v = top; v >= b0; v--) {
            int prev = running;              // count(> v)
            running += s_hist[v];            // count(>= v)
            if (prev < TOPK && running >= TOPK) {
                s_T = v;
                s_R = TOPK - prev;           // tie slots at value T
            }
        }
    }
    __syncthreads();

    int T = s_T;
    int R = s_R;

    // --- Phase C: ordered tie resolution via ballot + one 512-entry scan ---
    // column = s*1024 + wid*32 + lane → linear order is (s, wid, lane):
    // matches s_cnt index s*32 + wid.
    unsigned masks[16];
#pragma unroll
    for (int s = 0; s < 16; s++) {
        int flag = (ov[s] == T);
        unsigned m = __ballot_sync(0xffffffffu, flag);
        masks[s] = m;
        if (lane == 0) s_cnt[s * 32 + wid] = __popc(m);
    }
    __syncthreads();

    // exclusive scan of 512 counts by first 512 threads
    int v512 = 0, inc512 = 0;
    if (tid < 512) {
        v512 = s_cnt[tid];
        inc512 = warp_incl_scan(v512);
        if (lane == 31) s_warp[wid] = inc512;   // wid 0..15
    }
    __syncthreads();
    if (tid < 32) {
        int wv = (tid < 16) ? s_warp[tid] : 0;
        s_warp[tid] = warp_incl_scan(wv);
    }
    __syncthreads();
    if (tid < 512) {
        int add = (wid > 0) ? s_warp[wid - 1] : 0;
        s_cnt[tid] = inc512 - v512 + add;       // exclusive prefix
    }
    __syncthreads();

    unsigned lt = (1u << lane) - 1u;
#pragma unroll
    for (int s = 0; s < 16; s++) {
        int flag = (ov[s] == T);
        int rank = s_cnt[s * 32 + wid] + __popc(masks[s] & lt);
        float val = 0.0f;
        if (ov[s] > T) val = 1.0f;
        else if (flag && rank < R) val = 1.0f;
        out[s * 1024 + tid] = val;
    }
}

extern "C" void kernel_launch(void* const* d_in, const int* in_sizes, int n_in,
                              void* d_out, int out_size) {
    const int*   x = (const int*)d_in[0];
    const float* p = (const float*)d_in[1];
    if (in_sizes[0] != IN_DIM) {
        x = (const int*)d_in[1];
        p = (const float*)d_in[0];
    }
    float* out = (float*)d_out;

    prep_kernel<<<17, 1024>>>(x);
    dim3 grid(COL_BLOCKS, ROW_SPLITS);
    gemv_kernel<<<grid, 256>>>(p);
    topk_kernel<<<1, 1024>>>(out);
}

// round 4
// speedup vs baseline: 1.3851x; 1.0375x over previous
#include <cuda_runtime.h>

#define IN_DIM   8192
#define OUT_DIM  16384
#define TOPK     327
#define ROW_SPLITS 37                 // 16 * 37 = 592 = 4 * 148 SMs → one even wave
#define ROWS_PER_SPLIT 222            // ceil(8192 / 37)
#define COL_BLOCKS 16                 // 16 blocks * 256 thr * 4 cols = 16384 cols

__device__ int g_overlap[OUT_DIM];    // zero at module load; topk re-zeroes at end

__device__ __forceinline__ int warp_incl_scan(int v) {
    int lane = threadIdx.x & 31;
#pragma unroll
    for (int o = 1; o < 32; o <<= 1) {
        int n = __shfl_up_sync(0xffffffffu, v, o);
        if (lane >= o) v += n;
    }
    return v;
}

// ---------------------------------------------------------------------------
// Kernel 1: binarized GEMV. Each block compacts its own x-slice (deterministic
// ballot compaction), then streams the active rows of p with float4 loads.
// round(p) for p ~ U[0,1) under round-half-even == (p > 0.5f).
// ---------------------------------------------------------------------------
__global__ void __launch_bounds__(256, 4)
gemv_kernel(const float* __restrict__ p, const int* __restrict__ x) {
    __shared__ int s_act[ROWS_PER_SPLIT];
    __shared__ int s_wbase[8];
    __shared__ int s_na;

    int t    = threadIdx.x;
    int lane = t & 31;
    int w    = t >> 5;

    int r0 = blockIdx.y * ROWS_PER_SPLIT;
    int r1 = min(r0 + ROWS_PER_SPLIT, IN_DIM);
    int n  = r1 - r0;

    // --- per-block ordered compaction of the x slice ---
    int flag = 0;
    if (t < n) flag = (x[r0 + t] != 0);
    unsigned m = __ballot_sync(0xffffffffu, flag);
    int pos = __popc(m & ((1u << lane) - 1u));
    if (lane == 0) s_wbase[w] = __popc(m);
    __syncthreads();
    if (t < 8) {
        int v = s_wbase[t];
        int inc = v;
#pragma unroll
        for (int o = 1; o < 8; o <<= 1) {
            int u = __shfl_up_sync(0xffu, inc, o);
            if (t >= o) inc += u;
        }
        s_wbase[t] = inc - v;              // exclusive base
        if (t == 7) s_na = inc;
    }
    __syncthreads();
    if (flag) s_act[s_wbase[w] + pos] = r0 + t;
    __syncthreads();

    int na = s_na;

    // --- stream active rows, 8-deep for MLP ---
    int col = (blockIdx.x * blockDim.x + t) * 4;
    const float* pc = p + col;

    int c0 = 0, c1 = 0, c2 = 0, c3 = 0;
    int r = 0;
    for (; r + 8 <= na; r += 8) {
        float4 v[8];
#pragma unroll
        for (int u = 0; u < 8; u++)
            v[u] = *reinterpret_cast<const float4*>(pc + (size_t)s_act[r + u] * OUT_DIM);
#pragma unroll
        for (int u = 0; u < 8; u++) {
            c0 += (v[u].x > 0.5f);
            c1 += (v[u].y > 0.5f);
            c2 += (v[u].z > 0.5f);
            c3 += (v[u].w > 0.5f);
        }
    }
    for (; r < na; r++) {
        float4 v0 = *reinterpret_cast<const float4*>(pc + (size_t)s_act[r] * OUT_DIM);
        c0 += (v0.x > 0.5f);
        c1 += (v0.y > 0.5f);
        c2 += (v0.z > 0.5f);
        c3 += (v0.w > 0.5f);
    }

    if (c0) atomicAdd(&g_overlap[col + 0], c0);
    if (c1) atomicAdd(&g_overlap[col + 1], c1);
    if (c2) atomicAdd(&g_overlap[col + 2], c2);
    if (c3) atomicAdd(&g_overlap[col + 3], c3);
}

// ---------------------------------------------------------------------------
// Kernel 2: exact top-K with jax.lax.top_k tie semantics (lower index first).
// Single block, 1024 threads, shuffle/ballot scans. Re-zeroes g_overlap at the
// end so the next launch starts from a clean accumulator.
// ---------------------------------------------------------------------------
__global__ void topk_kernel(float* __restrict__ out) {
    __shared__ int s_hist[IN_DIM + 1];   // 8193 bins
    __shared__ int s_scan[1024];
    __shared__ int s_warp[32];
    __shared__ int s_cnt[512];           // per (segment, warp) tie counts
    __shared__ int s_T, s_R;

    int tid  = threadIdx.x;
    int lane = tid & 31;
    int wid  = tid >> 5;

    for (int i = tid; i <= IN_DIM; i += 1024) s_hist[i] = 0;
    __syncthreads();

    // --- Phase A: histogram ---
    int ov[16];
#pragma unroll
    for (int s = 0; s < 16; s++) {
        ov[s] = g_overlap[s * 1024 + tid];
        atomicAdd(&s_hist[ov[s]], 1);
    }
    __syncthreads();

    // --- Phase B: threshold search ---
    // thread t owns bins [8t, 8t+7]; thread 1023 also owns bin 8192.
    int b0 = tid * 8;
    int csum = 0;
#pragma unroll
    for (int k = 0; k < 8; k++) csum += s_hist[b0 + k];
    if (tid == 1023) csum += s_hist[IN_DIM];

    // reversed inclusive scan => suffix sums
    s_scan[1023 - tid] = csum;
    __syncthreads();
    {
        int v = s_scan[tid];
        int inc = warp_incl_scan(v);
        if (lane == 31) s_warp[wid] = inc;
        __syncthreads();
        if (wid == 0) {
            int wv = s_warp[lane];
            s_warp[lane] = warp_incl_scan(wv);
        }
        __syncthreads();
        int add = (wid > 0) ? s_warp[wid - 1] : 0;
        s_scan[tid] = inc + add;
    }
    __syncthreads();

    int above = (tid == 1023) ? 0 : s_scan[1022 - tid];

    {
        int running = above;
        int top = (tid == 1023) ? IN_DIM : (b0 + 7);
        for (int v = top; v >= b0; v--) {
            int prev = running;              // count(> v)
            running += s_hist[v];            // count(>= v)
            if (prev < TOPK && running >= TOPK) {
                s_T = v;
                s_R = TOPK - prev;           // tie slots at value T
            }
        }
    }
    __syncthreads();

    int T = s_T;
    int R = s_R;

    // --- Phase C: ordered tie resolution via ballot + one 512-entry scan ---
    unsigned masks[16];
#pragma unroll
    for (int s = 0; s < 16; s++) {
        int flag = (ov[s] == T);
        unsigned m = __ballot_sync(0xffffffffu, flag);
        masks[s] = m;
        if (lane == 0) s_cnt[s * 32 + wid] = __popc(m);
    }
    __syncthreads();

    int v512 = 0, inc512 = 0;
    if (tid < 512) {
        v512 = s_cnt[tid];
        inc512 = warp_incl_scan(v512);
        if (lane == 31) s_warp[wid] = inc512;   // wid 0..15
    }
    __syncthreads();
    if (tid < 32) {
        int wv = (tid < 16) ? s_warp[tid] : 0;
        s_warp[tid] = warp_incl_scan(wv);
    }
    __syncthreads();
    if (tid < 512) {
        int add = (wid > 0) ? s_warp[wid - 1] : 0;
        s_cnt[tid] = inc512 - v512 + add;       // exclusive prefix
    }
    __syncthreads();

    unsigned lt = (1u << lane) - 1u;
#pragma unroll
    for (int s = 0; s < 16; s++) {
        int flag = (ov[s] == T);
        int rank = s_cnt[s * 32 + wid] + __popc(masks[s] & lt);
        float val = 0.0f;
        if (ov[s] > T) val = 1.0f;
        else if (flag && rank < R) val = 1.0f;
        out[s * 1024 + tid] = val;
    }

    // --- reset accumulator for the next launch (deterministic invariant) ---
#pragma unroll
    for (int s = 0; s < 16; s++) g_overlap[s * 1024 + tid] = 0;
}

extern "C" void kernel_launch(void* const* d_in, const int* in_sizes, int n_in,
                              void* d_out, int out_size) {
    const int*   x = (const int*)d_in[0];
    const float* p = (const float*)d_in[1];
    if (in_sizes[0] != IN_DIM) {
        x = (const int*)d_in[1];
        p = (const float*)d_in[0];
    }
    float* out = (float*)d_out;

    dim3 grid(COL_BLOCKS, ROW_SPLITS);
    gemv_kernel<<<grid, 256>>>(p, x);
    topk_kernel<<<1, 1024>>>(out);
}